// round 2
// baseline (speedup 1.0000x reference)
#include <cuda_runtime.h>
#include <cuda_bf16.h>

#define N_NODES 50000
#define N_EDGES 800000
#define HID 64

// ---- scratch (static device globals; no allocation) ----
__device__ int   g_deg[N_NODES];
__device__ int   g_off[N_NODES + 1];
__device__ int   g_cur[N_NODES];
__device__ int   g_srcidx[N_EDGES];
__device__ float g_A[N_NODES * HID];
__device__ float g_B[N_NODES * HID];
__device__ float g_H[N_NODES * HID];

// ---------------- CSR build ----------------
__global__ void k_zero_deg() {
    int i = blockIdx.x * blockDim.x + threadIdx.x;
    if (i < N_NODES) g_deg[i] = 0;
}

// edge_index is int32 on device (JAX default x64-disabled downcasts int64->int32)
__global__ void k_count(const int* __restrict__ ei) {
    int e = blockIdx.x * blockDim.x + threadIdx.x;
    if (e < N_EDGES) {
        int dst = ei[N_EDGES + e];
        atomicAdd(&g_deg[dst], 1);
    }
}

// single-block exclusive scan of g_deg -> g_off, g_cur
__global__ void k_scan() {
    __shared__ int sh[1024];
    __shared__ int carry_s;
    int tid = threadIdx.x;
    if (tid == 0) carry_s = 0;
    __syncthreads();
    for (int base = 0; base < N_NODES; base += 1024) {
        int i = base + tid;
        int v = (i < N_NODES) ? g_deg[i] : 0;
        sh[tid] = v;
        __syncthreads();
        for (int ofs = 1; ofs < 1024; ofs <<= 1) {
            int t = (tid >= ofs) ? sh[tid - ofs] : 0;
            __syncthreads();
            sh[tid] += t;
            __syncthreads();
        }
        int incl = sh[tid];
        int carry = carry_s;
        if (i < N_NODES) {
            int off = carry + incl - v;
            g_off[i] = off;
            g_cur[i] = off;
        }
        __syncthreads();
        if (tid == 1023) carry_s = carry + incl;
        __syncthreads();
    }
    if (tid == 0) g_off[N_NODES] = carry_s;
}

__global__ void k_fill(const int* __restrict__ ei) {
    int e = blockIdx.x * blockDim.x + threadIdx.x;
    if (e < N_EDGES) {
        int dst = ei[N_EDGES + e];
        int src = ei[e];
        int pos = atomicAdd(&g_cur[dst], 1);
        g_srcidx[pos] = src;
    }
}

// ---------------- layer-1 node pre-GEMMs: A = x@(Wtop-Wbot)+b, B = x@Wbot ----
__global__ void k_nodeAB1(const float* __restrict__ x,
                          const float* __restrict__ w1a,
                          const float* __restrict__ b1a) {
    __shared__ float wd[16 * 64];
    __shared__ float wb[16 * 64];
    __shared__ float bsh[64];
    int tid = threadIdx.x;
    for (int i = tid; i < 16 * 64; i += 256) {
        float top = w1a[i];
        float bot = w1a[16 * 64 + i];
        wd[i] = top - bot;
        wb[i] = bot;
    }
    if (tid < 64) bsh[tid] = b1a[tid];
    __syncthreads();
    int warp = tid >> 5, lane = tid & 31;
    int node = blockIdx.x * 8 + warp;
    if (node >= N_NODES) return;

    float xown = (lane < 16) ? x[node * 16 + lane] : 0.f;
    float a0 = bsh[lane * 2], a1 = bsh[lane * 2 + 1];
    float c0 = 0.f, c1 = 0.f;
#pragma unroll
    for (int k = 0; k < 16; k++) {
        float xk = __shfl_sync(0xffffffffu, xown, k);
        float2 wdv = *(const float2*)&wd[k * 64 + lane * 2];
        float2 wbv = *(const float2*)&wb[k * 64 + lane * 2];
        a0 += xk * wdv.x; a1 += xk * wdv.y;
        c0 += xk * wbv.x; c1 += xk * wbv.y;
    }
    *(float2*)&g_A[node * 64 + lane * 2] = make_float2(a0, a1);
    *(float2*)&g_B[node * 64 + lane * 2] = make_float2(c0, c1);
}

// ---------------- edge gather + post-GEMM (used for both layers) ----------
// per node i: acc = sum_e relu(A[i] + B[src_e]); h = relu((acc/deg)@Wp + bp)
__global__ void k_gather(const float* __restrict__ Wp, const float* __restrict__ bp) {
    __shared__ float wsh[64 * 64];
    __shared__ float bsh[64];
    __shared__ float accsh[8][64];
    int tid = threadIdx.x;
    for (int i = tid; i < 64 * 64; i += 256) wsh[i] = Wp[i];
    if (tid < 64) bsh[tid] = bp[tid];
    __syncthreads();
    int warp = tid >> 5, lane = tid & 31;
    int node = blockIdx.x * 8 + warp;
    if (node >= N_NODES) return;

    int e0 = g_off[node], e1 = g_off[node + 1];
    float2 a = *(const float2*)&g_A[node * 64 + lane * 2];
    float acc0 = 0.f, acc1 = 0.f;
    int e = e0;
    int s_next = (e < e1) ? g_srcidx[e] : 0;
    while (e < e1) {
        int s = s_next;
        ++e;
        if (e < e1) s_next = g_srcidx[e];
        float2 bb = *(const float2*)&g_B[s * 64 + lane * 2];
        acc0 += fmaxf(a.x + bb.x, 0.f);
        acc1 += fmaxf(a.y + bb.y, 0.f);
    }
    int deg = e1 - e0;
    float o0 = 0.f, o1 = 0.f;
    if (deg > 0) {
        float inv = 1.0f / (float)deg;
        acc0 *= inv; acc1 *= inv;
        accsh[warp][lane * 2] = acc0;
        accsh[warp][lane * 2 + 1] = acc1;
        __syncwarp();
        o0 = bsh[lane * 2]; o1 = bsh[lane * 2 + 1];
#pragma unroll 8
        for (int k = 0; k < 64; k++) {
            float av = accsh[warp][k];
            float2 w = *(const float2*)&wsh[k * 64 + lane * 2];
            o0 += av * w.x;
            o1 += av * w.y;
        }
        o0 = fmaxf(o0, 0.f);
        o1 = fmaxf(o1, 0.f);
    }
    *(float2*)&g_H[node * 64 + lane * 2] = make_float2(o0, o1);
}

// ---------------- layer-2 node pre-GEMMs from H (2 nodes per warp) ---------
__global__ void k_nodeAB2(const float* __restrict__ w2a,
                          const float* __restrict__ b2a) {
    __shared__ float wd[64 * 64];
    __shared__ float wb[64 * 64];
    __shared__ float bsh[64];
    int tid = threadIdx.x;
    for (int i = tid; i < 64 * 64; i += 256) {
        float top = w2a[i];
        float bot = w2a[64 * 64 + i];
        wd[i] = top - bot;
        wb[i] = bot;
    }
    if (tid < 64) bsh[tid] = b2a[tid];
    __syncthreads();
    int warp = tid >> 5, lane = tid & 31;
    int n0 = (blockIdx.x * 8 + warp) * 2;
    if (n0 >= N_NODES) return;
    bool has1 = (n0 + 1) < N_NODES;

    float2 h0 = *(const float2*)&g_H[n0 * 64 + lane * 2];
    float2 h1 = has1 ? *(const float2*)&g_H[(n0 + 1) * 64 + lane * 2]
                     : make_float2(0.f, 0.f);
    float bias0 = bsh[lane * 2], bias1 = bsh[lane * 2 + 1];
    float a00 = bias0, a01 = bias1, c00 = 0.f, c01 = 0.f;
    float a10 = bias0, a11 = bias1, c10 = 0.f, c11 = 0.f;
#pragma unroll
    for (int k2 = 0; k2 < 32; k2++) {
        float hx0 = __shfl_sync(0xffffffffu, h0.x, k2);
        float hy0 = __shfl_sync(0xffffffffu, h0.y, k2);
        float hx1 = __shfl_sync(0xffffffffu, h1.x, k2);
        float hy1 = __shfl_sync(0xffffffffu, h1.y, k2);
        float2 wdv = *(const float2*)&wd[(2 * k2) * 64 + lane * 2];
        float2 wbv = *(const float2*)&wb[(2 * k2) * 64 + lane * 2];
        a00 += hx0 * wdv.x; a01 += hx0 * wdv.y;
        c00 += hx0 * wbv.x; c01 += hx0 * wbv.y;
        a10 += hx1 * wdv.x; a11 += hx1 * wdv.y;
        c10 += hx1 * wbv.x; c11 += hx1 * wbv.y;
        wdv = *(const float2*)&wd[(2 * k2 + 1) * 64 + lane * 2];
        wbv = *(const float2*)&wb[(2 * k2 + 1) * 64 + lane * 2];
        a00 += hy0 * wdv.x; a01 += hy0 * wdv.y;
        c00 += hy0 * wbv.x; c01 += hy0 * wbv.y;
        a10 += hy1 * wdv.x; a11 += hy1 * wdv.y;
        c10 += hy1 * wbv.x; c11 += hy1 * wbv.y;
    }
    *(float2*)&g_A[n0 * 64 + lane * 2] = make_float2(a00, a01);
    *(float2*)&g_B[n0 * 64 + lane * 2] = make_float2(c00, c01);
    if (has1) {
        *(float2*)&g_A[(n0 + 1) * 64 + lane * 2] = make_float2(a10, a11);
        *(float2*)&g_B[(n0 + 1) * 64 + lane * 2] = make_float2(c10, c11);
    }
}

// ---------------- final projection: out = H@wl + bl --------------------
__global__ void k_final(const float* __restrict__ wl,
                        const float* __restrict__ bl,
                        float* __restrict__ out) {
    int warp = threadIdx.x >> 5, lane = threadIdx.x & 31;
    int node = blockIdx.x * 8 + warp;
    if (node >= N_NODES) return;
    float2 h = *(const float2*)&g_H[node * 64 + lane * 2];
    float4 w = *(const float4*)&wl[lane * 4];  // rows 2l, 2l+1 of [64,2]
    float p0 = h.x * w.x + h.y * w.z;
    float p1 = h.x * w.y + h.y * w.w;
#pragma unroll
    for (int o = 16; o > 0; o >>= 1) {
        p0 += __shfl_xor_sync(0xffffffffu, p0, o);
        p1 += __shfl_xor_sync(0xffffffffu, p1, o);
    }
    if (lane == 0) {
        out[node * 2 + 0] = p0 + bl[0];
        out[node * 2 + 1] = p1 + bl[1];
    }
}

extern "C" void kernel_launch(void* const* d_in, const int* in_sizes, int n_in,
                              void* d_out, int out_size) {
    const float* x   = (const float*)d_in[0];
    const int*   ei  = (const int*)d_in[1];   // int32 (JAX default x64 disabled)
    const float* w1a = (const float*)d_in[2];
    const float* b1a = (const float*)d_in[3];
    const float* w1b = (const float*)d_in[4];
    const float* b1b = (const float*)d_in[5];
    const float* w2a = (const float*)d_in[6];
    const float* b2a = (const float*)d_in[7];
    const float* w2b = (const float*)d_in[8];
    const float* b2b = (const float*)d_in[9];
    const float* wl  = (const float*)d_in[10];
    const float* bl  = (const float*)d_in[11];
    float* out = (float*)d_out;

    // CSR build (identical for both layers)
    k_zero_deg<<<(N_NODES + 255) / 256, 256>>>();
    k_count<<<(N_EDGES + 255) / 256, 256>>>(ei);
    k_scan<<<1, 1024>>>();
    k_fill<<<(N_EDGES + 255) / 256, 256>>>(ei);

    // layer 1
    k_nodeAB1<<<(N_NODES + 7) / 8, 256>>>(x, w1a, b1a);
    k_gather<<<(N_NODES + 7) / 8, 256>>>(w1b, b1b);

    // layer 2
    k_nodeAB2<<<(N_NODES / 2 + 7) / 8, 256>>>(w2a, b2a);
    k_gather<<<(N_NODES + 7) / 8, 256>>>(w2b, b2b);

    // output projection
    k_final<<<(N_NODES + 7) / 8, 256>>>(wl, bl, out);
}

// round 3
// speedup vs baseline: 1.8394x; 1.8394x over previous
#include <cuda_runtime.h>
#include <cuda_bf16.h>

#define N_NODES 50000
#define N_EDGES 800000
#define HID 64
#define SCAN_BLOCKS ((N_NODES + 255) / 256)   // 196

// ---- scratch (static device globals; no allocation) ----
__device__ int   g_deg[N_NODES];
__device__ int   g_off[N_NODES + 1];
__device__ int   g_cur[N_NODES];
__device__ int   g_bsum[256];
__device__ int   g_bpre[256];
__device__ int   g_srcidx[N_EDGES];
__device__ float g_A[N_NODES * HID];
__device__ float g_B[N_NODES * HID];
__device__ float g_H[N_NODES * HID];

// ---- packed f32x2 helpers (FFMA2: 2x FFMA rate, identical .rn rounding) ----
__device__ __forceinline__ unsigned long long pack2(float x, float y) {
    unsigned long long r;
    asm("mov.b64 %0, {%1, %2};" : "=l"(r) : "f"(x), "f"(y));
    return r;
}
__device__ __forceinline__ void unpack2(unsigned long long v, float& x, float& y) {
    asm("mov.b64 {%0, %1}, %2;" : "=f"(x), "=f"(y) : "l"(v));
}
__device__ __forceinline__ void fma2(unsigned long long& acc, unsigned long long a,
                                     unsigned long long b) {
    asm("fma.rn.f32x2 %0, %1, %2, %0;" : "+l"(acc) : "l"(a), "l"(b));
}

// ---------------- CSR build ----------------
__global__ void k_zero_deg() {
    int i = blockIdx.x * blockDim.x + threadIdx.x;
    if (i < N_NODES) g_deg[i] = 0;
}

__global__ void k_count(const int* __restrict__ ei) {
    int e = blockIdx.x * blockDim.x + threadIdx.x;
    if (e < N_EDGES) atomicAdd(&g_deg[ei[N_EDGES + e]], 1);
}

// multi-block exclusive scan: scan1 (per-block) -> scan2 (block sums) -> scan3 (apply)
__global__ void k_scan1() {
    __shared__ int sh[256];
    int tid = threadIdx.x;
    int i = blockIdx.x * 256 + tid;
    int v = (i < N_NODES) ? g_deg[i] : 0;
    sh[tid] = v;
    __syncthreads();
#pragma unroll
    for (int ofs = 1; ofs < 256; ofs <<= 1) {
        int t = (tid >= ofs) ? sh[tid - ofs] : 0;
        __syncthreads();
        sh[tid] += t;
        __syncthreads();
    }
    if (i < N_NODES) g_off[i] = sh[tid] - v;     // exclusive within block
    if (tid == 255) g_bsum[blockIdx.x] = sh[255];
}

__global__ void k_scan2() {
    __shared__ int sh[256];
    int tid = threadIdx.x;
    int v = (tid < SCAN_BLOCKS) ? g_bsum[tid] : 0;
    sh[tid] = v;
    __syncthreads();
#pragma unroll
    for (int ofs = 1; ofs < 256; ofs <<= 1) {
        int t = (tid >= ofs) ? sh[tid - ofs] : 0;
        __syncthreads();
        sh[tid] += t;
        __syncthreads();
    }
    g_bpre[tid] = sh[tid] - v;
    if (tid == 255) g_off[N_NODES] = sh[255];
}

__global__ void k_scan3() {
    int i = blockIdx.x * 256 + threadIdx.x;
    if (i < N_NODES) {
        int v = g_off[i] + g_bpre[blockIdx.x];
        g_off[i] = v;
        g_cur[i] = v;
    }
}

__global__ void k_fill(const int* __restrict__ ei) {
    int e = blockIdx.x * blockDim.x + threadIdx.x;
    if (e < N_EDGES) {
        int dst = ei[N_EDGES + e];
        int src = ei[e];
        int pos = atomicAdd(&g_cur[dst], 1);
        g_srcidx[pos] = src;
    }
}

// ---------------- layer-1 node pre-GEMMs: A = x@(Wtop-Wbot)+b, B = x@Wbot ----
// 4 nodes per warp to amortize the weight smem load.
__global__ void __launch_bounds__(256) k_nodeAB1(const float* __restrict__ x,
                                                 const float* __restrict__ w1a,
                                                 const float* __restrict__ b1a) {
    __shared__ float wd[16 * 64];
    __shared__ float wb[16 * 64];
    __shared__ float bshm[64];
    int tid = threadIdx.x;
    for (int i = tid; i < 16 * 64; i += 256) {
        float top = w1a[i];
        float bot = w1a[16 * 64 + i];
        wd[i] = top - bot;
        wb[i] = bot;
    }
    if (tid < 64) bshm[tid] = b1a[tid];
    __syncthreads();
    int warp = tid >> 5, lane = tid & 31;
    int nbase = (blockIdx.x * 8 + warp) * 4;
#pragma unroll
    for (int ni = 0; ni < 4; ni++) {
        int node = nbase + ni;
        if (node >= N_NODES) break;
        float xown = (lane < 16) ? x[node * 16 + lane] : 0.f;
        unsigned long long A = pack2(bshm[2 * lane], bshm[2 * lane + 1]);
        unsigned long long C = 0ULL;
#pragma unroll
        for (int k = 0; k < 16; k++) {
            float xk = __shfl_sync(0xffffffffu, xown, k);
            unsigned long long x2 = pack2(xk, xk);
            unsigned long long wdv = *(const unsigned long long*)&wd[k * 64 + lane * 2];
            unsigned long long wbv = *(const unsigned long long*)&wb[k * 64 + lane * 2];
            fma2(A, x2, wdv);
            fma2(C, x2, wbv);
        }
        float ax, ay, cx, cy;
        unpack2(A, ax, ay);
        unpack2(C, cx, cy);
        *(float2*)&g_A[node * 64 + lane * 2] = make_float2(ax, ay);
        *(float2*)&g_B[node * 64 + lane * 2] = make_float2(cx, cy);
    }
}

// ---------------- edge gather + post-GEMM (both layers; FINAL fuses projection)
// per node i: acc = mean_e relu(A[i] + B[src_e]); h = relu(acc@Wp + bp)
// FINAL=1: out[i] = h@wl + bl (warp-reduced), no H write.
template <int FINAL>
__global__ void __launch_bounds__(256) k_gather_t(const float* __restrict__ Wp,
                                                  const float* __restrict__ bp,
                                                  const float* __restrict__ wl,
                                                  const float* __restrict__ bl,
                                                  float* __restrict__ out) {
    __shared__ float wsh[64 * 64];
    __shared__ float bshm[64];
    __shared__ float accsh[8][64][4];   // [warp][channel][node-in-warp]
    int tid = threadIdx.x;
    for (int i = tid; i < 64 * 64; i += 256) wsh[i] = Wp[i];
    if (tid < 64) bshm[tid] = bp[tid];
    __syncthreads();
    int warp = tid >> 5, lane = tid & 31;
    int nbase = (blockIdx.x * 8 + warp) * 4;

    int dg[4];
#pragma unroll
    for (int ni = 0; ni < 4; ni++) {
        int node = nbase + ni;
        float acc0 = 0.f, acc1 = 0.f;
        int deg = 0;
        if (node < N_NODES) {
            int e0 = g_off[node], e1 = g_off[node + 1];
            deg = e1 - e0;
            float2 a = *(const float2*)&g_A[node * 64 + lane * 2];
            int e = e0;
            for (; e + 4 <= e1; e += 4) {          // MLP=4
                int s0 = g_srcidx[e], s1 = g_srcidx[e + 1];
                int s2 = g_srcidx[e + 2], s3 = g_srcidx[e + 3];
                float2 b0 = *(const float2*)&g_B[s0 * 64 + lane * 2];
                float2 b1 = *(const float2*)&g_B[s1 * 64 + lane * 2];
                float2 b2 = *(const float2*)&g_B[s2 * 64 + lane * 2];
                float2 b3 = *(const float2*)&g_B[s3 * 64 + lane * 2];
                acc0 += fmaxf(a.x + b0.x, 0.f); acc1 += fmaxf(a.y + b0.y, 0.f);
                acc0 += fmaxf(a.x + b1.x, 0.f); acc1 += fmaxf(a.y + b1.y, 0.f);
                acc0 += fmaxf(a.x + b2.x, 0.f); acc1 += fmaxf(a.y + b2.y, 0.f);
                acc0 += fmaxf(a.x + b3.x, 0.f); acc1 += fmaxf(a.y + b3.y, 0.f);
            }
            for (; e < e1; e++) {
                int s = g_srcidx[e];
                float2 bb = *(const float2*)&g_B[s * 64 + lane * 2];
                acc0 += fmaxf(a.x + bb.x, 0.f);
                acc1 += fmaxf(a.y + bb.y, 0.f);
            }
            if (deg > 0) {
                float inv = 1.0f / (float)deg;
                acc0 *= inv;
                acc1 *= inv;
            }
        }
        dg[ni] = deg;
        accsh[warp][2 * lane][ni] = acc0;
        accsh[warp][2 * lane + 1][ni] = acc1;
    }
    __syncwarp();

    // fused 4-node epilogue GEMM in packed f32x2
    unsigned long long accA[4];
    {
        unsigned long long binit = pack2(bshm[2 * lane], bshm[2 * lane + 1]);
#pragma unroll
        for (int ni = 0; ni < 4; ni++) accA[ni] = binit;
    }
#pragma unroll 8
    for (int k = 0; k < 64; k++) {
        float4 av = *(const float4*)&accsh[warp][k][0];   // 4 nodes' channel-k
        unsigned long long w2 = *(const unsigned long long*)&wsh[k * 64 + 2 * lane];
        fma2(accA[0], pack2(av.x, av.x), w2);
        fma2(accA[1], pack2(av.y, av.y), w2);
        fma2(accA[2], pack2(av.z, av.z), w2);
        fma2(accA[3], pack2(av.w, av.w), w2);
    }

    if (FINAL == 0) {
#pragma unroll
        for (int ni = 0; ni < 4; ni++) {
            int node = nbase + ni;
            if (node >= N_NODES) break;
            float o0, o1;
            unpack2(accA[ni], o0, o1);
            if (dg[ni] > 0) { o0 = fmaxf(o0, 0.f); o1 = fmaxf(o1, 0.f); }
            else           { o0 = 0.f; o1 = 0.f; }
            *(float2*)&g_H[node * 64 + lane * 2] = make_float2(o0, o1);
        }
    } else {
        float4 w = *(const float4*)&wl[lane * 4];   // wl rows 2l, 2l+1 of [64,2]
        float bl0 = bl[0], bl1 = bl[1];
#pragma unroll
        for (int ni = 0; ni < 4; ni++) {
            int node = nbase + ni;
            if (node >= N_NODES) break;
            float o0, o1;
            unpack2(accA[ni], o0, o1);
            if (dg[ni] > 0) { o0 = fmaxf(o0, 0.f); o1 = fmaxf(o1, 0.f); }
            else           { o0 = 0.f; o1 = 0.f; }
            float p0 = o0 * w.x + o1 * w.z;
            float p1 = o0 * w.y + o1 * w.w;
#pragma unroll
            for (int ofs = 16; ofs > 0; ofs >>= 1) {
                p0 += __shfl_xor_sync(0xffffffffu, p0, ofs);
                p1 += __shfl_xor_sync(0xffffffffu, p1, ofs);
            }
            if (lane == 0) {
                out[node * 2 + 0] = p0 + bl0;
                out[node * 2 + 1] = p1 + bl1;
            }
        }
    }
}

// ---------------- layer-2 node pre-GEMMs from H: 8 nodes per warp, f32x2 ----
__global__ void __launch_bounds__(256) k_nodeAB2(const float* __restrict__ w2a,
                                                 const float* __restrict__ b2a) {
    __shared__ float wdb[64 * 32 * 4];   // [(k*32+lane)*4] = {wd.x, wd.y, wb.x, wb.y}
    __shared__ float bshm[64];
    __shared__ float hsh[8][64 * 8];     // [warp][channel*8 + node]
    int tid = threadIdx.x;
    for (int idx = tid; idx < 64 * 64; idx += 256) {
        int k = idx >> 6, col = idx & 63;
        float top = w2a[idx];
        float bot = w2a[64 * 64 + idx];
        int ln = col >> 1, comp = col & 1;
        wdb[(k * 32 + ln) * 4 + comp]     = top - bot;
        wdb[(k * 32 + ln) * 4 + 2 + comp] = bot;
    }
    if (tid < 64) bshm[tid] = b2a[tid];
    __syncthreads();
    int warp = tid >> 5, lane = tid & 31;
    int nbase = (blockIdx.x * 8 + warp) * 8;

#pragma unroll
    for (int ni = 0; ni < 8; ni++) {
        int node = nbase + ni;
        float2 h = (node < N_NODES) ? *(const float2*)&g_H[node * 64 + lane * 2]
                                    : make_float2(0.f, 0.f);
        hsh[warp][(2 * lane) * 8 + ni]     = h.x;
        hsh[warp][(2 * lane + 1) * 8 + ni] = h.y;
    }
    __syncwarp();

    unsigned long long A[8], C[8];
    unsigned long long binit = pack2(bshm[2 * lane], bshm[2 * lane + 1]);
#pragma unroll
    for (int ni = 0; ni < 8; ni++) { A[ni] = binit; C[ni] = 0ULL; }

#pragma unroll 4
    for (int k = 0; k < 64; k++) {
        float4 h03 = *(const float4*)&hsh[warp][k * 8];
        float4 h47 = *(const float4*)&hsh[warp][k * 8 + 4];
        const unsigned long long* wp =
            (const unsigned long long*)&wdb[(k * 32 + lane) * 4];
        unsigned long long wd2 = wp[0], wb2 = wp[1];
        unsigned long long hh;
        hh = pack2(h03.x, h03.x); fma2(A[0], hh, wd2); fma2(C[0], hh, wb2);
        hh = pack2(h03.y, h03.y); fma2(A[1], hh, wd2); fma2(C[1], hh, wb2);
        hh = pack2(h03.z, h03.z); fma2(A[2], hh, wd2); fma2(C[2], hh, wb2);
        hh = pack2(h03.w, h03.w); fma2(A[3], hh, wd2); fma2(C[3], hh, wb2);
        hh = pack2(h47.x, h47.x); fma2(A[4], hh, wd2); fma2(C[4], hh, wb2);
        hh = pack2(h47.y, h47.y); fma2(A[5], hh, wd2); fma2(C[5], hh, wb2);
        hh = pack2(h47.z, h47.z); fma2(A[6], hh, wd2); fma2(C[6], hh, wb2);
        hh = pack2(h47.w, h47.w); fma2(A[7], hh, wd2); fma2(C[7], hh, wb2);
    }
#pragma unroll
    for (int ni = 0; ni < 8; ni++) {
        int node = nbase + ni;
        if (node >= N_NODES) break;
        float ax, ay, cx, cy;
        unpack2(A[ni], ax, ay);
        unpack2(C[ni], cx, cy);
        *(float2*)&g_A[node * 64 + lane * 2] = make_float2(ax, ay);
        *(float2*)&g_B[node * 64 + lane * 2] = make_float2(cx, cy);
    }
}

extern "C" void kernel_launch(void* const* d_in, const int* in_sizes, int n_in,
                              void* d_out, int out_size) {
    const float* x   = (const float*)d_in[0];
    const int*   ei  = (const int*)d_in[1];   // int32 (JAX default x64 disabled)
    const float* w1a = (const float*)d_in[2];
    const float* b1a = (const float*)d_in[3];
    const float* w1b = (const float*)d_in[4];
    const float* b1b = (const float*)d_in[5];
    const float* w2a = (const float*)d_in[6];
    const float* b2a = (const float*)d_in[7];
    const float* w2b = (const float*)d_in[8];
    const float* b2b = (const float*)d_in[9];
    const float* wl  = (const float*)d_in[10];
    const float* bl  = (const float*)d_in[11];
    float* out = (float*)d_out;

    // CSR build
    k_zero_deg<<<SCAN_BLOCKS, 256>>>();
    k_count<<<(N_EDGES + 255) / 256, 256>>>(ei);
    k_scan1<<<SCAN_BLOCKS, 256>>>();
    k_scan2<<<1, 256>>>();
    k_scan3<<<SCAN_BLOCKS, 256>>>();
    k_fill<<<(N_EDGES + 255) / 256, 256>>>(ei);

    int gather_blocks = (N_NODES + 31) / 32;   // 8 warps x 4 nodes
    int ab2_blocks    = (N_NODES + 63) / 64;   // 8 warps x 8 nodes

    // layer 1
    k_nodeAB1<<<gather_blocks, 256>>>(x, w1a, b1a);
    k_gather_t<0><<<gather_blocks, 256>>>(w1b, b1b, wl, bl, out);

    // layer 2 (+ fused final projection)
    k_nodeAB2<<<ab2_blocks, 256>>>(w2a, b2a);
    k_gather_t<1><<<gather_blocks, 256>>>(w2b, b2b, wl, bl, out);
}

// round 4
// speedup vs baseline: 1.9468x; 1.0584x over previous
#include <cuda_runtime.h>
#include <cuda_fp16.h>

#define N_NODES 50000
#define N_EDGES 800000
#define HID 64
#define SCAN_BLOCKS ((N_NODES + 255) / 256)   // 196

// ---- scratch (static device globals; no allocation) ----
__device__ int    g_deg[N_NODES];
__device__ int    g_off[N_NODES + 1];
__device__ int    g_rank[N_EDGES];
__device__ int    g_bsum[256];
__device__ int    g_srcidx[N_EDGES];
__device__ float  g_A[N_NODES * HID];
__device__ __half g_Bh[N_NODES * HID];    // B table in fp16 (halves gather traffic)
__device__ float  g_H[N_NODES * HID];

// ---- packed f32x2 helpers (FFMA2: 2x FFMA rate, identical .rn rounding) ----
__device__ __forceinline__ unsigned long long pack2(float x, float y) {
    unsigned long long r;
    asm("mov.b64 %0, {%1, %2};" : "=l"(r) : "f"(x), "f"(y));
    return r;
}
__device__ __forceinline__ void unpack2(unsigned long long v, float& x, float& y) {
    asm("mov.b64 {%0, %1}, %2;" : "=f"(x), "=f"(y) : "l"(v));
}
__device__ __forceinline__ void fma2(unsigned long long& acc, unsigned long long a,
                                     unsigned long long b) {
    asm("fma.rn.f32x2 %0, %1, %2, %0;" : "+l"(acc) : "l"(a), "l"(b));
}

// ---------------- CSR build ----------------
__global__ void k_zero_deg() {
    int i = blockIdx.x * blockDim.x + threadIdx.x;
    if (i < N_NODES) g_deg[i] = 0;
}

// single atomic pass: degree histogram AND per-edge rank within its dst bucket
__global__ void k_count(const int* __restrict__ ei) {
    int e = blockIdx.x * blockDim.x + threadIdx.x;
    if (e < N_EDGES) g_rank[e] = atomicAdd(&g_deg[ei[N_EDGES + e]], 1);
}

// per-block exclusive scan of g_deg -> g_off (partial), block totals -> g_bsum
__global__ void k_scan1() {
    __shared__ int sh[256];
    int tid = threadIdx.x;
    int i = blockIdx.x * 256 + tid;
    int v = (i < N_NODES) ? g_deg[i] : 0;
    sh[tid] = v;
    __syncthreads();
#pragma unroll
    for (int ofs = 1; ofs < 256; ofs <<= 1) {
        int t = (tid >= ofs) ? sh[tid - ofs] : 0;
        __syncthreads();
        sh[tid] += t;
        __syncthreads();
    }
    if (i < N_NODES) g_off[i] = sh[tid] - v;     // exclusive within block
    if (tid == 255) g_bsum[blockIdx.x] = sh[255];
}

// merged scan2+scan3: every block redundantly scans the 196 block sums,
// then applies its own block's exclusive prefix to g_off
__global__ void k_scan23() {
    __shared__ int sh[256];
    int tid = threadIdx.x;
    int v = (tid < SCAN_BLOCKS) ? g_bsum[tid] : 0;
    sh[tid] = v;
    __syncthreads();
#pragma unroll
    for (int ofs = 1; ofs < 256; ofs <<= 1) {
        int t = (tid >= ofs) ? sh[tid - ofs] : 0;
        __syncthreads();
        sh[tid] += t;
        __syncthreads();
    }
    int prefix = (blockIdx.x == 0) ? 0 : sh[blockIdx.x - 1];
    int i = blockIdx.x * 256 + tid;
    if (i < N_NODES) g_off[i] += prefix;
    if (blockIdx.x == 0 && tid == 0) g_off[N_NODES] = sh[255];
}

// atomic-free fill: position = off[dst] + rank[e]
__global__ void k_fill(const int* __restrict__ ei) {
    int e = blockIdx.x * blockDim.x + threadIdx.x;
    if (e < N_EDGES) {
        int dst = ei[N_EDGES + e];
        g_srcidx[g_off[dst] + g_rank[e]] = ei[e];
    }
}

// ---------------- layer-1 node pre-GEMMs: A = x@(Wtop-Wbot)+b, B = x@Wbot ----
__global__ void __launch_bounds__(256) k_nodeAB1(const float* __restrict__ x,
                                                 const float* __restrict__ w1a,
                                                 const float* __restrict__ b1a) {
    __shared__ float wd[16 * 64];
    __shared__ float wb[16 * 64];
    __shared__ float bshm[64];
    int tid = threadIdx.x;
    for (int i = tid; i < 16 * 64; i += 256) {
        float top = w1a[i];
        float bot = w1a[16 * 64 + i];
        wd[i] = top - bot;
        wb[i] = bot;
    }
    if (tid < 64) bshm[tid] = b1a[tid];
    __syncthreads();
    int warp = tid >> 5, lane = tid & 31;
    int nbase = (blockIdx.x * 8 + warp) * 4;
#pragma unroll
    for (int ni = 0; ni < 4; ni++) {
        int node = nbase + ni;
        if (node >= N_NODES) break;
        float xown = (lane < 16) ? x[node * 16 + lane] : 0.f;
        unsigned long long A = pack2(bshm[2 * lane], bshm[2 * lane + 1]);
        unsigned long long C = 0ULL;
#pragma unroll
        for (int k = 0; k < 16; k++) {
            float xk = __shfl_sync(0xffffffffu, xown, k);
            unsigned long long x2 = pack2(xk, xk);
            unsigned long long wdv = *(const unsigned long long*)&wd[k * 64 + lane * 2];
            unsigned long long wbv = *(const unsigned long long*)&wb[k * 64 + lane * 2];
            fma2(A, x2, wdv);
            fma2(C, x2, wbv);
        }
        float ax, ay, cx, cy;
        unpack2(A, ax, ay);
        unpack2(C, cx, cy);
        *(float2*)&g_A[node * 64 + lane * 2] = make_float2(ax, ay);
        ((__half2*)g_Bh)[node * 32 + lane] = __floats2half2_rn(cx, cy);
    }
}

// ---------------- edge gather + post-GEMM (both layers; FINAL fuses projection)
// per node i: acc = mean_e relu(A[i] + B[src_e]); h = relu(acc@Wp + bp)
template <int FINAL>
__global__ void __launch_bounds__(256) k_gather_t(const float* __restrict__ Wp,
                                                  const float* __restrict__ bp,
                                                  const float* __restrict__ wl,
                                                  const float* __restrict__ bl,
                                                  float* __restrict__ out) {
    __shared__ float wsh[64 * 64];
    __shared__ float bshm[64];
    __shared__ float accsh[8][64][4];   // [warp][channel][node-in-warp]
    int tid = threadIdx.x;
    for (int i = tid; i < 64 * 64; i += 256) wsh[i] = Wp[i];
    if (tid < 64) bshm[tid] = bp[tid];
    __syncthreads();
    int warp = tid >> 5, lane = tid & 31;
    int nbase = (blockIdx.x * 8 + warp) * 4;
    const __half2* __restrict__ Bh2 = (const __half2*)g_Bh;

    int dg[4];
#pragma unroll
    for (int ni = 0; ni < 4; ni++) {
        int node = nbase + ni;
        float acc0 = 0.f, acc1 = 0.f;
        int deg = 0;
        if (node < N_NODES) {
            int e0 = g_off[node], e1 = g_off[node + 1];
            deg = e1 - e0;
            float2 a = *(const float2*)&g_A[node * 64 + lane * 2];
            int e = e0;
            for (; e + 4 <= e1; e += 4) {          // MLP=4
                int s0 = g_srcidx[e], s1 = g_srcidx[e + 1];
                int s2 = g_srcidx[e + 2], s3 = g_srcidx[e + 3];
                float2 b0 = __half22float2(Bh2[s0 * 32 + lane]);
                float2 b1 = __half22float2(Bh2[s1 * 32 + lane]);
                float2 b2 = __half22float2(Bh2[s2 * 32 + lane]);
                float2 b3 = __half22float2(Bh2[s3 * 32 + lane]);
                acc0 += fmaxf(a.x + b0.x, 0.f); acc1 += fmaxf(a.y + b0.y, 0.f);
                acc0 += fmaxf(a.x + b1.x, 0.f); acc1 += fmaxf(a.y + b1.y, 0.f);
                acc0 += fmaxf(a.x + b2.x, 0.f); acc1 += fmaxf(a.y + b2.y, 0.f);
                acc0 += fmaxf(a.x + b3.x, 0.f); acc1 += fmaxf(a.y + b3.y, 0.f);
            }
            for (; e < e1; e++) {
                int s = g_srcidx[e];
                float2 bb = __half22float2(Bh2[s * 32 + lane]);
                acc0 += fmaxf(a.x + bb.x, 0.f);
                acc1 += fmaxf(a.y + bb.y, 0.f);
            }
            if (deg > 0) {
                float inv = 1.0f / (float)deg;
                acc0 *= inv;
                acc1 *= inv;
            }
        }
        dg[ni] = deg;
        accsh[warp][2 * lane][ni] = acc0;
        accsh[warp][2 * lane + 1][ni] = acc1;
    }
    __syncwarp();

    // fused 4-node epilogue GEMM in packed f32x2
    unsigned long long accA[4];
    {
        unsigned long long binit = pack2(bshm[2 * lane], bshm[2 * lane + 1]);
#pragma unroll
        for (int ni = 0; ni < 4; ni++) accA[ni] = binit;
    }
#pragma unroll 8
    for (int k = 0; k < 64; k++) {
        float4 av = *(const float4*)&accsh[warp][k][0];
        unsigned long long w2 = *(const unsigned long long*)&wsh[k * 64 + 2 * lane];
        fma2(accA[0], pack2(av.x, av.x), w2);
        fma2(accA[1], pack2(av.y, av.y), w2);
        fma2(accA[2], pack2(av.z, av.z), w2);
        fma2(accA[3], pack2(av.w, av.w), w2);
    }

    if (FINAL == 0) {
#pragma unroll
        for (int ni = 0; ni < 4; ni++) {
            int node = nbase + ni;
            if (node >= N_NODES) break;
            float o0, o1;
            unpack2(accA[ni], o0, o1);
            if (dg[ni] > 0) { o0 = fmaxf(o0, 0.f); o1 = fmaxf(o1, 0.f); }
            else            { o0 = 0.f; o1 = 0.f; }
            *(float2*)&g_H[node * 64 + lane * 2] = make_float2(o0, o1);
        }
    } else {
        float4 w = *(const float4*)&wl[lane * 4];
        float bl0 = bl[0], bl1 = bl[1];
#pragma unroll
        for (int ni = 0; ni < 4; ni++) {
            int node = nbase + ni;
            if (node >= N_NODES) break;
            float o0, o1;
            unpack2(accA[ni], o0, o1);
            if (dg[ni] > 0) { o0 = fmaxf(o0, 0.f); o1 = fmaxf(o1, 0.f); }
            else            { o0 = 0.f; o1 = 0.f; }
            float p0 = o0 * w.x + o1 * w.z;
            float p1 = o0 * w.y + o1 * w.w;
#pragma unroll
            for (int ofs = 16; ofs > 0; ofs >>= 1) {
                p0 += __shfl_xor_sync(0xffffffffu, p0, ofs);
                p1 += __shfl_xor_sync(0xffffffffu, p1, ofs);
            }
            if (lane == 0) {
                out[node * 2 + 0] = p0 + bl0;
                out[node * 2 + 1] = p1 + bl1;
            }
        }
    }
}

// ---------------- layer-2 node pre-GEMMs from H: 8 nodes per warp, f32x2 ----
__global__ void __launch_bounds__(256) k_nodeAB2(const float* __restrict__ w2a,
                                                 const float* __restrict__ b2a) {
    __shared__ float wdb[64 * 32 * 4];   // [(k*32+lane)*4] = {wd.x, wd.y, wb.x, wb.y}
    __shared__ float bshm[64];
    __shared__ float hsh[8][64 * 8];     // [warp][channel*8 + node]
    int tid = threadIdx.x;
    for (int idx = tid; idx < 64 * 64; idx += 256) {
        int k = idx >> 6, col = idx & 63;
        float top = w2a[idx];
        float bot = w2a[64 * 64 + idx];
        int ln = col >> 1, comp = col & 1;
        wdb[(k * 32 + ln) * 4 + comp]     = top - bot;
        wdb[(k * 32 + ln) * 4 + 2 + comp] = bot;
    }
    if (tid < 64) bshm[tid] = b2a[tid];
    __syncthreads();
    int warp = tid >> 5, lane = tid & 31;
    int nbase = (blockIdx.x * 8 + warp) * 8;

#pragma unroll
    for (int ni = 0; ni < 8; ni++) {
        int node = nbase + ni;
        float2 h = (node < N_NODES) ? *(const float2*)&g_H[node * 64 + lane * 2]
                                    : make_float2(0.f, 0.f);
        hsh[warp][(2 * lane) * 8 + ni]     = h.x;
        hsh[warp][(2 * lane + 1) * 8 + ni] = h.y;
    }
    __syncwarp();

    unsigned long long A[8], C[8];
    unsigned long long binit = pack2(bshm[2 * lane], bshm[2 * lane + 1]);
#pragma unroll
    for (int ni = 0; ni < 8; ni++) { A[ni] = binit; C[ni] = 0ULL; }

#pragma unroll 4
    for (int k = 0; k < 64; k++) {
        float4 h03 = *(const float4*)&hsh[warp][k * 8];
        float4 h47 = *(const float4*)&hsh[warp][k * 8 + 4];
        const unsigned long long* wp =
            (const unsigned long long*)&wdb[(k * 32 + lane) * 4];
        unsigned long long wd2 = wp[0], wb2 = wp[1];
        unsigned long long hh;
        hh = pack2(h03.x, h03.x); fma2(A[0], hh, wd2); fma2(C[0], hh, wb2);
        hh = pack2(h03.y, h03.y); fma2(A[1], hh, wd2); fma2(C[1], hh, wb2);
        hh = pack2(h03.z, h03.z); fma2(A[2], hh, wd2); fma2(C[2], hh, wb2);
        hh = pack2(h03.w, h03.w); fma2(A[3], hh, wd2); fma2(C[3], hh, wb2);
        hh = pack2(h47.x, h47.x); fma2(A[4], hh, wd2); fma2(C[4], hh, wb2);
        hh = pack2(h47.y, h47.y); fma2(A[5], hh, wd2); fma2(C[5], hh, wb2);
        hh = pack2(h47.z, h47.z); fma2(A[6], hh, wd2); fma2(C[6], hh, wb2);
        hh = pack2(h47.w, h47.w); fma2(A[7], hh, wd2); fma2(C[7], hh, wb2);
    }
#pragma unroll
    for (int ni = 0; ni < 8; ni++) {
        int node = nbase + ni;
        if (node >= N_NODES) break;
        float ax, ay, cx, cy;
        unpack2(A[ni], ax, ay);
        unpack2(C[ni], cx, cy);
        *(float2*)&g_A[node * 64 + lane * 2] = make_float2(ax, ay);
        ((__half2*)g_Bh)[node * 32 + lane] = __floats2half2_rn(cx, cy);
    }
}

extern "C" void kernel_launch(void* const* d_in, const int* in_sizes, int n_in,
                              void* d_out, int out_size) {
    const float* x   = (const float*)d_in[0];
    const int*   ei  = (const int*)d_in[1];   // int32 (JAX default x64 disabled)
    const float* w1a = (const float*)d_in[2];
    const float* b1a = (const float*)d_in[3];
    const float* w1b = (const float*)d_in[4];
    const float* b1b = (const float*)d_in[5];
    const float* w2a = (const float*)d_in[6];
    const float* b2a = (const float*)d_in[7];
    const float* w2b = (const float*)d_in[8];
    const float* b2b = (const float*)d_in[9];
    const float* wl  = (const float*)d_in[10];
    const float* bl  = (const float*)d_in[11];
    float* out = (float*)d_out;

    // CSR build: zero -> count(+rank) -> scan1 -> scan23 -> fill (atomic-free)
    k_zero_deg<<<SCAN_BLOCKS, 256>>>();
    k_count<<<(N_EDGES + 255) / 256, 256>>>(ei);
    k_scan1<<<SCAN_BLOCKS, 256>>>();
    k_scan23<<<SCAN_BLOCKS, 256>>>();
    k_fill<<<(N_EDGES + 255) / 256, 256>>>(ei);

    int gather_blocks = (N_NODES + 31) / 32;   // 8 warps x 4 nodes
    int ab2_blocks    = (N_NODES + 63) / 64;   // 8 warps x 8 nodes

    // layer 1
    k_nodeAB1<<<gather_blocks, 256>>>(x, w1a, b1a);
    k_gather_t<0><<<gather_blocks, 256>>>(w1b, b1b, wl, bl, out);

    // layer 2 (+ fused final projection)
    k_nodeAB2<<<ab2_blocks, 256>>>(w2a, b2a);
    k_gather_t<1><<<gather_blocks, 256>>>(w2b, b2b, wl, bl, out);
}

// round 5
// speedup vs baseline: 2.0117x; 1.0333x over previous
#include <cuda_runtime.h>
#include <cuda_fp16.h>

#define N_NODES 50000
#define N_EDGES 800000
#define HID 64
#define SCAN_BLOCKS ((N_NODES + 255) / 256)   // 196

// ---- scratch (static device globals; zero-initialized at load) ----
__device__ int    g_deg[N_NODES];       // re-zeroed by k_scan23 each call
__device__ int    g_off[N_NODES + 1];
__device__ int    g_rank[N_EDGES];
__device__ int    g_bsum[256];
__device__ int    g_srcidx[N_EDGES];
__device__ float  g_A[N_NODES * HID];
__device__ __half g_Bh[N_NODES * HID];  // B table in fp16 (halves gather traffic)
__device__ float  g_H[N_NODES * HID];

// ---- packed f32x2 helpers (FFMA2: 2x FFMA rate, identical .rn rounding) ----
__device__ __forceinline__ unsigned long long pack2(float x, float y) {
    unsigned long long r;
    asm("mov.b64 %0, {%1, %2};" : "=l"(r) : "f"(x), "f"(y));
    return r;
}
__device__ __forceinline__ void unpack2(unsigned long long v, float& x, float& y) {
    asm("mov.b64 {%0, %1}, %2;" : "=f"(x), "=f"(y) : "l"(v));
}
__device__ __forceinline__ void fma2(unsigned long long& acc, unsigned long long a,
                                     unsigned long long b) {
    asm("fma.rn.f32x2 %0, %1, %2, %0;" : "+l"(acc) : "l"(a), "l"(b));
}

// ---------------- CSR build ----------------
// single atomic pass: degree histogram AND per-edge rank within its dst bucket
// (g_deg is guaranteed zero on entry: zero-init at load + re-zeroed by k_scan23)
__global__ void k_count(const int* __restrict__ ei) {
    int e = blockIdx.x * blockDim.x + threadIdx.x;
    if (e < N_EDGES) g_rank[e] = atomicAdd(&g_deg[ei[N_EDGES + e]], 1);
}

// per-block exclusive scan of g_deg -> g_off (partial), block totals -> g_bsum
__global__ void k_scan1() {
    __shared__ int sh[256];
    int tid = threadIdx.x;
    int i = blockIdx.x * 256 + tid;
    int v = (i < N_NODES) ? g_deg[i] : 0;
    sh[tid] = v;
    __syncthreads();
#pragma unroll
    for (int ofs = 1; ofs < 256; ofs <<= 1) {
        int t = (tid >= ofs) ? sh[tid - ofs] : 0;
        __syncthreads();
        sh[tid] += t;
        __syncthreads();
    }
    if (i < N_NODES) g_off[i] = sh[tid] - v;     // exclusive within block
    if (tid == 255) g_bsum[blockIdx.x] = sh[255];
}

// merged scan2+scan3: every block redundantly scans the 196 block sums,
// applies its block's prefix to g_off, and re-zeroes g_deg for the next call
__global__ void k_scan23() {
    __shared__ int sh[256];
    int tid = threadIdx.x;
    int v = (tid < SCAN_BLOCKS) ? g_bsum[tid] : 0;
    sh[tid] = v;
    __syncthreads();
#pragma unroll
    for (int ofs = 1; ofs < 256; ofs <<= 1) {
        int t = (tid >= ofs) ? sh[tid - ofs] : 0;
        __syncthreads();
        sh[tid] += t;
        __syncthreads();
    }
    int prefix = (blockIdx.x == 0) ? 0 : sh[blockIdx.x - 1];
    int i = blockIdx.x * 256 + tid;
    if (i < N_NODES) {
        g_off[i] += prefix;
        g_deg[i] = 0;                            // invariant for next invocation
    }
    if (blockIdx.x == 0 && tid == 0) g_off[N_NODES] = sh[255];
}

// atomic-free fill: position = off[dst] + rank[e]
__global__ void k_fill(const int* __restrict__ ei) {
    int e = blockIdx.x * blockDim.x + threadIdx.x;
    if (e < N_EDGES) {
        int dst = ei[N_EDGES + e];
        g_srcidx[g_off[dst] + g_rank[e]] = ei[e];
    }
}

// ---------------- layer-1 node pre-GEMMs: A = x@(Wtop-Wbot)+b, B = x@Wbot ----
__global__ void __launch_bounds__(256) k_nodeAB1(const float* __restrict__ x,
                                                 const float* __restrict__ w1a,
                                                 const float* __restrict__ b1a) {
    __shared__ float wd[16 * 64];
    __shared__ float wb[16 * 64];
    __shared__ float bshm[64];
    int tid = threadIdx.x;
    for (int i = tid; i < 16 * 64; i += 256) {
        float top = w1a[i];
        float bot = w1a[16 * 64 + i];
        wd[i] = top - bot;
        wb[i] = bot;
    }
    if (tid < 64) bshm[tid] = b1a[tid];
    __syncthreads();
    int warp = tid >> 5, lane = tid & 31;
    int nbase = (blockIdx.x * 8 + warp) * 4;
#pragma unroll
    for (int ni = 0; ni < 4; ni++) {
        int node = nbase + ni;
        if (node >= N_NODES) break;
        float xown = (lane < 16) ? x[node * 16 + lane] : 0.f;
        unsigned long long A = pack2(bshm[2 * lane], bshm[2 * lane + 1]);
        unsigned long long C = 0ULL;
#pragma unroll
        for (int k = 0; k < 16; k++) {
            float xk = __shfl_sync(0xffffffffu, xown, k);
            unsigned long long x2 = pack2(xk, xk);
            unsigned long long wdv = *(const unsigned long long*)&wd[k * 64 + lane * 2];
            unsigned long long wbv = *(const unsigned long long*)&wb[k * 64 + lane * 2];
            fma2(A, x2, wdv);
            fma2(C, x2, wbv);
        }
        float ax, ay, cx, cy;
        unpack2(A, ax, ay);
        unpack2(C, cx, cy);
        *(float2*)&g_A[node * 64 + lane * 2] = make_float2(ax, ay);
        ((__half2*)g_Bh)[node * 32 + lane] = __floats2half2_rn(cx, cy);
    }
}

// ---------------- edge gather + post-GEMM (both layers; FINAL fuses projection)
// per node i: acc = mean_e relu(A[i] + B[src_e]); h = relu(acc@Wp + bp)
template <int FINAL>
__global__ void __launch_bounds__(256) k_gather_t(const float* __restrict__ Wp,
                                                  const float* __restrict__ bp,
                                                  const float* __restrict__ wl,
                                                  const float* __restrict__ bl,
                                                  float* __restrict__ out) {
    __shared__ float wsh[64 * 64];
    __shared__ float bshm[64];
    __shared__ float accsh[8][64][4];   // [warp][channel][node-in-warp]
    int tid = threadIdx.x;
    for (int i = tid; i < 64 * 64; i += 256) wsh[i] = Wp[i];
    if (tid < 64) bshm[tid] = bp[tid];
    __syncthreads();
    int warp = tid >> 5, lane = tid & 31;
    int nbase = (blockIdx.x * 8 + warp) * 4;
    const __half2* __restrict__ Bh2 = (const __half2*)g_Bh;

    int dg[4];
#pragma unroll
    for (int ni = 0; ni < 4; ni++) {
        int node = nbase + ni;
        float acc0 = 0.f, acc1 = 0.f;
        int deg = 0;
        if (node < N_NODES) {
            int e0 = g_off[node], e1 = g_off[node + 1];
            deg = e1 - e0;
            float2 a = *(const float2*)&g_A[node * 64 + lane * 2];
            int e = e0;
            // MLP=8: batch 8 index loads, then 8 row loads
            for (; e + 8 <= e1; e += 8) {
                int s[8];
#pragma unroll
                for (int j = 0; j < 8; j++) s[j] = g_srcidx[e + j];
                float2 b[8];
#pragma unroll
                for (int j = 0; j < 8; j++) b[j] = __half22float2(Bh2[s[j] * 32 + lane]);
#pragma unroll
                for (int j = 0; j < 8; j++) {
                    acc0 += fmaxf(a.x + b[j].x, 0.f);
                    acc1 += fmaxf(a.y + b[j].y, 0.f);
                }
            }
            if (e + 4 <= e1) {
                int s[4];
#pragma unroll
                for (int j = 0; j < 4; j++) s[j] = g_srcidx[e + j];
                float2 b[4];
#pragma unroll
                for (int j = 0; j < 4; j++) b[j] = __half22float2(Bh2[s[j] * 32 + lane]);
#pragma unroll
                for (int j = 0; j < 4; j++) {
                    acc0 += fmaxf(a.x + b[j].x, 0.f);
                    acc1 += fmaxf(a.y + b[j].y, 0.f);
                }
                e += 4;
            }
            for (; e < e1; e++) {
                int s = g_srcidx[e];
                float2 bb = __half22float2(Bh2[s * 32 + lane]);
                acc0 += fmaxf(a.x + bb.x, 0.f);
                acc1 += fmaxf(a.y + bb.y, 0.f);
            }
            if (deg > 0) {
                float inv = 1.0f / (float)deg;
                acc0 *= inv;
                acc1 *= inv;
            }
        }
        dg[ni] = deg;
        accsh[warp][2 * lane][ni] = acc0;
        accsh[warp][2 * lane + 1][ni] = acc1;
    }
    __syncwarp();

    // fused 4-node epilogue GEMM in packed f32x2
    unsigned long long accA[4];
    {
        unsigned long long binit = pack2(bshm[2 * lane], bshm[2 * lane + 1]);
#pragma unroll
        for (int ni = 0; ni < 4; ni++) accA[ni] = binit;
    }
#pragma unroll 8
    for (int k = 0; k < 64; k++) {
        float4 av = *(const float4*)&accsh[warp][k][0];
        unsigned long long w2 = *(const unsigned long long*)&wsh[k * 64 + 2 * lane];
        fma2(accA[0], pack2(av.x, av.x), w2);
        fma2(accA[1], pack2(av.y, av.y), w2);
        fma2(accA[2], pack2(av.z, av.z), w2);
        fma2(accA[3], pack2(av.w, av.w), w2);
    }

    if (FINAL == 0) {
#pragma unroll
        for (int ni = 0; ni < 4; ni++) {
            int node = nbase + ni;
            if (node >= N_NODES) break;
            float o0, o1;
            unpack2(accA[ni], o0, o1);
            if (dg[ni] > 0) { o0 = fmaxf(o0, 0.f); o1 = fmaxf(o1, 0.f); }
            else            { o0 = 0.f; o1 = 0.f; }
            *(float2*)&g_H[node * 64 + lane * 2] = make_float2(o0, o1);
        }
    } else {
        float4 w = *(const float4*)&wl[lane * 4];
        float bl0 = bl[0], bl1 = bl[1];
#pragma unroll
        for (int ni = 0; ni < 4; ni++) {
            int node = nbase + ni;
            if (node >= N_NODES) break;
            float o0, o1;
            unpack2(accA[ni], o0, o1);
            if (dg[ni] > 0) { o0 = fmaxf(o0, 0.f); o1 = fmaxf(o1, 0.f); }
            else            { o0 = 0.f; o1 = 0.f; }
            float p0 = o0 * w.x + o1 * w.z;
            float p1 = o0 * w.y + o1 * w.w;
#pragma unroll
            for (int ofs = 16; ofs > 0; ofs >>= 1) {
                p0 += __shfl_xor_sync(0xffffffffu, p0, ofs);
                p1 += __shfl_xor_sync(0xffffffffu, p1, ofs);
            }
            if (lane == 0) {
                out[node * 2 + 0] = p0 + bl0;
                out[node * 2 + 1] = p1 + bl1;
            }
        }
    }
}

// ---------------- layer-2 node pre-GEMMs from H: 8 nodes per warp, f32x2 ----
__global__ void __launch_bounds__(256) k_nodeAB2(const float* __restrict__ w2a,
                                                 const float* __restrict__ b2a) {
    __shared__ float wdb[64 * 32 * 4];   // [(k*32+lane)*4] = {wd.x, wd.y, wb.x, wb.y}
    __shared__ float bshm[64];
    __shared__ float hsh[8][64 * 8];     // [warp][channel*8 + node]
    int tid = threadIdx.x;
    for (int idx = tid; idx < 64 * 64; idx += 256) {
        int k = idx >> 6, col = idx & 63;
        float top = w2a[idx];
        float bot = w2a[64 * 64 + idx];
        int ln = col >> 1, comp = col & 1;
        wdb[(k * 32 + ln) * 4 + comp]     = top - bot;
        wdb[(k * 32 + ln) * 4 + 2 + comp] = bot;
    }
    if (tid < 64) bshm[tid] = b2a[tid];
    __syncthreads();
    int warp = tid >> 5, lane = tid & 31;
    int nbase = (blockIdx.x * 8 + warp) * 8;

#pragma unroll
    for (int ni = 0; ni < 8; ni++) {
        int node = nbase + ni;
        float2 h = (node < N_NODES) ? *(const float2*)&g_H[node * 64 + lane * 2]
                                    : make_float2(0.f, 0.f);
        hsh[warp][(2 * lane) * 8 + ni]     = h.x;
        hsh[warp][(2 * lane + 1) * 8 + ni] = h.y;
    }
    __syncwarp();

    unsigned long long A[8], C[8];
    unsigned long long binit = pack2(bshm[2 * lane], bshm[2 * lane + 1]);
#pragma unroll
    for (int ni = 0; ni < 8; ni++) { A[ni] = binit; C[ni] = 0ULL; }

#pragma unroll 4
    for (int k = 0; k < 64; k++) {
        float4 h03 = *(const float4*)&hsh[warp][k * 8];
        float4 h47 = *(const float4*)&hsh[warp][k * 8 + 4];
        const unsigned long long* wp =
            (const unsigned long long*)&wdb[(k * 32 + lane) * 4];
        unsigned long long wd2 = wp[0], wb2 = wp[1];
        unsigned long long hh;
        hh = pack2(h03.x, h03.x); fma2(A[0], hh, wd2); fma2(C[0], hh, wb2);
        hh = pack2(h03.y, h03.y); fma2(A[1], hh, wd2); fma2(C[1], hh, wb2);
        hh = pack2(h03.z, h03.z); fma2(A[2], hh, wd2); fma2(C[2], hh, wb2);
        hh = pack2(h03.w, h03.w); fma2(A[3], hh, wd2); fma2(C[3], hh, wb2);
        hh = pack2(h47.x, h47.x); fma2(A[4], hh, wd2); fma2(C[4], hh, wb2);
        hh = pack2(h47.y, h47.y); fma2(A[5], hh, wd2); fma2(C[5], hh, wb2);
        hh = pack2(h47.z, h47.z); fma2(A[6], hh, wd2); fma2(C[6], hh, wb2);
        hh = pack2(h47.w, h47.w); fma2(A[7], hh, wd2); fma2(C[7], hh, wb2);
    }
#pragma unroll
    for (int ni = 0; ni < 8; ni++) {
        int node = nbase + ni;
        if (node >= N_NODES) break;
        float ax, ay, cx, cy;
        unpack2(A[ni], ax, ay);
        unpack2(C[ni], cx, cy);
        *(float2*)&g_A[node * 64 + lane * 2] = make_float2(ax, ay);
        ((__half2*)g_Bh)[node * 32 + lane] = __floats2half2_rn(cx, cy);
    }
}

extern "C" void kernel_launch(void* const* d_in, const int* in_sizes, int n_in,
                              void* d_out, int out_size) {
    const float* x   = (const float*)d_in[0];
    const int*   ei  = (const int*)d_in[1];   // int32 (JAX default x64 disabled)
    const float* w1a = (const float*)d_in[2];
    const float* b1a = (const float*)d_in[3];
    const float* w1b = (const float*)d_in[4];
    const float* b1b = (const float*)d_in[5];
    const float* w2a = (const float*)d_in[6];
    const float* b2a = (const float*)d_in[7];
    const float* w2b = (const float*)d_in[8];
    const float* b2b = (const float*)d_in[9];
    const float* wl  = (const float*)d_in[10];
    const float* bl  = (const float*)d_in[11];
    float* out = (float*)d_out;

    // CSR build: count(+rank) -> scan1 -> scan23(+re-zero deg) -> fill
    k_count<<<(N_EDGES + 255) / 256, 256>>>(ei);
    k_scan1<<<SCAN_BLOCKS, 256>>>();
    k_scan23<<<SCAN_BLOCKS, 256>>>();
    k_fill<<<(N_EDGES + 255) / 256, 256>>>(ei);

    int gather_blocks = (N_NODES + 31) / 32;   // 8 warps x 4 nodes
    int ab2_blocks    = (N_NODES + 63) / 64;   // 8 warps x 8 nodes

    // layer 1
    k_nodeAB1<<<gather_blocks, 256>>>(x, w1a, b1a);
    k_gather_t<0><<<gather_blocks, 256>>>(w1b, b1b, wl, bl, out);

    // layer 2 (+ fused final projection)
    k_nodeAB2<<<ab2_blocks, 256>>>(w2a, b2a);
    k_gather_t<1><<<gather_blocks, 256>>>(w2b, b2b, wl, bl, out);
}